// round 1
// baseline (speedup 1.0000x reference)
#include <cuda_runtime.h>
#include <cuda_bf16.h>

// Problem shapes (fixed for this dataset entry)
#define BB 1024   // batch
#define CC 1000   // classes
#define HH 512    // hidden

#define NEG_INF (__int_as_float(0xff800000))

// Scratch (allocation-free rule: __device__ globals)
// Gram split-K partials: G[kh][p*1024 + q] = sum over H-half kh of w[p]·w[q]
__device__ float g_G[2][1024 * 1024];   // 8 MB
__device__ float g_norm[CC];
__device__ float g_ymax[BB];
__device__ int   g_jmax[BB];

// ---------------------------------------------------------------------------
// packed fp32x2 helpers (FFMA2 — only reachable via PTX fma.rn.f32x2)
// ---------------------------------------------------------------------------
__device__ __forceinline__ void fma2(unsigned long long& acc,
                                     unsigned long long a,
                                     unsigned long long b) {
    asm("fma.rn.f32x2 %0, %1, %2, %0;" : "+l"(acc) : "l"(a), "l"(b));
}
__device__ __forceinline__ unsigned long long bcast2(float v) {
    unsigned long long r;
    unsigned u = __float_as_uint(v);
    asm("mov.b64 %0, {%1, %1};" : "=l"(r) : "r"(u));
    return r;
}
__device__ __forceinline__ float lo32(unsigned long long u) {
    return __uint_as_float((unsigned)u);
}
__device__ __forceinline__ float hi32(unsigned long long u) {
    return __uint_as_float((unsigned)(u >> 32));
}

// ---------------------------------------------------------------------------
// Kernel 1: fused per-row argmax/max of y (+ copy y into out[:, :CC])
//           and per-row squared norms of w.
// grid = BB + CC blocks, 256 threads
// ---------------------------------------------------------------------------
__global__ void k_prep(const float* __restrict__ y,
                       const float* __restrict__ w,
                       float* __restrict__ out) {
    const int t = threadIdx.x;
    __shared__ float sv[256];
    __shared__ int   si[256];

    const int bb = blockIdx.x;
    if (bb < BB) {
        const float* yr = y + (long)bb * CC;
        float* orow = out + (long)bb * (CC + 1);
        float vmax = NEG_INF;
        int imax = 0;
        for (int c = t; c < CC; c += 256) {
            float v = yr[c];
            orow[c] = v;                       // fused copy
            if (v > vmax) { vmax = v; imax = c; }
        }
        sv[t] = vmax; si[t] = imax;
        __syncthreads();
        #pragma unroll
        for (int s = 128; s > 0; s >>= 1) {
            if (t < s) {
                float v2 = sv[t + s]; int i2 = si[t + s];
                if (v2 > sv[t] || (v2 == sv[t] && i2 < si[t])) {
                    sv[t] = v2; si[t] = i2;    // first-index tie-break (jnp.argmax)
                }
            }
            __syncthreads();
        }
        if (t == 0) { g_ymax[bb] = sv[0]; g_jmax[bb] = si[0]; }
    } else {
        const int c = bb - BB;
        const float* wr = w + (long)c * HH;
        float s = 0.f;
        for (int h = t; h < HH; h += 256) {
            float v = wr[h];
            s = fmaf(v, v, s);
        }
        sv[t] = s;
        __syncthreads();
        #pragma unroll
        for (int s2 = 128; s2 > 0; s2 >>= 1) {
            if (t < s2) sv[t] += sv[t + s2];
            __syncthreads();
        }
        if (t == 0) g_norm[c] = sv[0];
    }
}

// ---------------------------------------------------------------------------
// Kernel 2: symmetric Gram G = w @ w^T, upper-triangular tile pairs only,
// split-K into 2 halves (deterministic: separate output buffers, no atomics).
// grid = (136, 2), 128 threads. Tile 64x64, BK=16, micro-tile 8x4 via FFMA2.
// ---------------------------------------------------------------------------
#define NT 16          // ceil(1000/64)
#define BK 16
#define SMS 66         // smem row stride (even: keeps LDS.64 8B-aligned)

__global__ void __launch_bounds__(128, 2)
k_gram(const float* __restrict__ w) {
    // decode upper-triangular pair index -> (ti, tj), ti <= tj
    int p = blockIdx.x;
    int ti = 0;
    while (p >= NT - ti) { p -= NT - ti; ti++; }
    const int tj = ti + p;
    const int kh = blockIdx.y;            // K-half: [kh*256, kh*256+256)
    const int k0 = kh * (HH / 2);

    __shared__ float As[BK][SMS];         // transposed: As[kk][row]
    __shared__ float Bs[BK][SMS];

    const int t   = threadIdx.x;
    const int seg = t & 3;                // which float4 within a 16-float chunk
    const int rr  = t >> 2;               // 0..31

    const int aR0 = min(ti * 64 + rr,      CC - 1);
    const int aR1 = min(ti * 64 + rr + 32, CC - 1);
    const int bR0 = min(tj * 64 + rr,      CC - 1);
    const int bR1 = min(tj * 64 + rr + 32, CC - 1);
    const float* pa0 = w + (long)aR0 * HH + k0 + seg * 4;
    const float* pa1 = w + (long)aR1 * HH + k0 + seg * 4;
    const float* pb0 = w + (long)bR0 * HH + k0 + seg * 4;
    const float* pb1 = w + (long)bR1 * HH + k0 + seg * 4;

    const int tr8 = (t >> 4) * 8;         // 8-row group base (0..56)
    const int tc4 = (t & 15) * 4;         // 4-col group base (0..60)

    unsigned long long acc[4][4];
    #pragma unroll
    for (int i = 0; i < 4; i++)
        #pragma unroll
        for (int j = 0; j < 4; j++) acc[i][j] = 0ull;

    #pragma unroll 1
    for (int ks = 0; ks < (HH / 2) / BK; ks++) {
        // issue global loads first (overlap with prior compute)
        const float4 va0 = *(const float4*)(pa0 + ks * BK);
        const float4 va1 = *(const float4*)(pa1 + ks * BK);
        const float4 vb0 = *(const float4*)(pb0 + ks * BK);
        const float4 vb1 = *(const float4*)(pb1 + ks * BK);

        __syncthreads();   // previous tile fully consumed
        As[seg * 4 + 0][rr]      = va0.x;  As[seg * 4 + 1][rr]      = va0.y;
        As[seg * 4 + 2][rr]      = va0.z;  As[seg * 4 + 3][rr]      = va0.w;
        As[seg * 4 + 0][rr + 32] = va1.x;  As[seg * 4 + 1][rr + 32] = va1.y;
        As[seg * 4 + 2][rr + 32] = va1.z;  As[seg * 4 + 3][rr + 32] = va1.w;
        Bs[seg * 4 + 0][rr]      = vb0.x;  Bs[seg * 4 + 1][rr]      = vb0.y;
        Bs[seg * 4 + 2][rr]      = vb0.z;  Bs[seg * 4 + 3][rr]      = vb0.w;
        Bs[seg * 4 + 0][rr + 32] = vb1.x;  Bs[seg * 4 + 1][rr + 32] = vb1.y;
        Bs[seg * 4 + 2][rr + 32] = vb1.z;  Bs[seg * 4 + 3][rr + 32] = vb1.w;
        __syncthreads();

        #pragma unroll
        for (int kk = 0; kk < BK; kk++) {
            const unsigned long long a0 = *(const unsigned long long*)&As[kk][tr8 + 0];
            const unsigned long long a1 = *(const unsigned long long*)&As[kk][tr8 + 2];
            const unsigned long long a2 = *(const unsigned long long*)&As[kk][tr8 + 4];
            const unsigned long long a3 = *(const unsigned long long*)&As[kk][tr8 + 6];
            #pragma unroll
            for (int c = 0; c < 4; c++) {
                const unsigned long long bb2 = bcast2(Bs[kk][tc4 + c]);
                fma2(acc[0][c], a0, bb2);
                fma2(acc[1][c], a1, bb2);
                fma2(acc[2][c], a2, bb2);
                fma2(acc[3][c], a3, bb2);
            }
        }
    }

    // epilogue: store tile to G[kh] (upper-triangle tiles only; no mirror —
    // the consumer does a triangle lookup). Rows/cols beyond CC fall into the
    // 1024-stride padding, never read.
    float* Gout = &g_G[kh][0];
    const int gr = ti * 64 + tr8;
    const int gc = tj * 64 + tc4;
    #pragma unroll
    for (int rp = 0; rp < 4; rp++) {
        float4 vlo, vhi;
        vlo.x = lo32(acc[rp][0]); vlo.y = lo32(acc[rp][1]);
        vlo.z = lo32(acc[rp][2]); vlo.w = lo32(acc[rp][3]);
        vhi.x = hi32(acc[rp][0]); vhi.y = hi32(acc[rp][1]);
        vhi.z = hi32(acc[rp][2]); vhi.w = hi32(acc[rp][3]);
        *(float4*)&Gout[(long)(gr + 2 * rp)     * 1024 + gc] = vlo;
        *(float4*)&Gout[(long)(gr + 2 * rp + 1) * 1024 + gc] = vhi;
    }
}

// ---------------------------------------------------------------------------
// Kernel 3: y_bot[b] = max_{c : y[b,c] != ymax[b]} ( y[b,c] + eps*|L|*sqrt(sq) )
// one warp per row; sqrt pruned against the running max (conservative test,
// correct for any sign of eps*L).
// ---------------------------------------------------------------------------
__global__ void k_bot(const float* __restrict__ y,
                      const float* __restrict__ eps_p,
                      const float* __restrict__ lip_p,
                      float* __restrict__ out) {
    const int gwarp = (blockIdx.x * blockDim.x + threadIdx.x) >> 5;
    const int lane  = threadIdx.x & 31;
    if (gwarp >= BB) return;
    const int b = gwarp;

    const float s  = (*eps_p) * fabsf(*lip_p);
    const float s2 = s * s;

    const int   j    = g_jmax[b];
    const float ymax = g_ymax[b];
    const float nj   = g_norm[j];
    const float* yr  = y + (long)b * CC;
    const float* G0  = &g_G[0][0];
    const float* G1  = &g_G[1][0];

    float best = NEG_INF;
    for (int c = lane; c < CC; c += 32) {
        const float yv = yr[c];
        if (yv == ymax) continue;          // exact-equality mask, matches ref
        const int idx = (j <= c) ? (j * 1024 + c) : (c * 1024 + j);
        const float dot = G0[idx] + G1[idx];
        float sq = nj + g_norm[c] - 2.f * dot;
        if (sq < 0.f) sq = 0.f;            // safe sqrt (matches ref where())
        const float d = best - yv;
        // skip only when provably val <= best:  |s|*sqrt(sq) <= d  (d > 0)
        if (d <= 0.f || sq * s2 > d * d) {
            const float val = fmaf(s, sqrtf(sq), yv);
            best = fmaxf(best, val);
        }
    }
    #pragma unroll
    for (int o = 16; o > 0; o >>= 1)
        best = fmaxf(best, __shfl_xor_sync(0xffffffffu, best, o));
    if (lane == 0) out[(long)b * (CC + 1) + CC] = best;
}

// ---------------------------------------------------------------------------
extern "C" void kernel_launch(void* const* d_in, const int* in_sizes, int n_in,
                              void* d_out, int out_size) {
    const float* y   = (const float*)d_in[0];
    const float* w   = (const float*)d_in[1];
    const float* eps = (const float*)d_in[2];
    const float* lip = (const float*)d_in[3];
    float* out = (float*)d_out;

    k_prep<<<BB + CC, 256>>>(y, w, out);

    dim3 g2(NT * (NT + 1) / 2, 2);   // 136 tile-pairs x 2 K-halves
    k_gram<<<g2, 128>>>(w);

    k_bot<<<BB / 8, 256>>>(y, eps, lip, out);   // 8 warps/block, 1 warp/row
}

// round 2
// speedup vs baseline: 1.3312x; 1.3312x over previous
#include <cuda_runtime.h>
#include <cuda_bf16.h>

#define BB 1024
#define CC 1000
#define HH 512
#define NEG_INF (__int_as_float(0xff800000))

// scratch
__device__ float g_G[1024 * 1024];   // full symmetric Gram, 4MB
__device__ float g_norm[1024];
__device__ float g_ymax[BB];
__device__ int   g_jmax[BB];

typedef unsigned long long ull;

__device__ __forceinline__ void fma2(ull& acc, ull a, ull b) {
    asm("fma.rn.f32x2 %0, %1, %2, %0;" : "+l"(acc) : "l"(a), "l"(b));
}
__device__ __forceinline__ float lo32(ull u) { return __uint_as_float((unsigned)u); }
__device__ __forceinline__ float hi32(ull u) { return __uint_as_float((unsigned)(u >> 32)); }

// ---------------------------------------------------------------------------
// k_prep: warp-per-row. rows [0,BB): y argmax/max + copy into out.
//         rows [BB, BB+CC): w squared norms.
// ---------------------------------------------------------------------------
__global__ void k_prep(const float* __restrict__ y,
                       const float* __restrict__ w,
                       float* __restrict__ out) {
    const int warp = (blockIdx.x * blockDim.x + threadIdx.x) >> 5;
    const int lane = threadIdx.x & 31;

    if (warp < BB) {
        const int b = warp;
        const float4* yr = (const float4*)(y + (long)b * CC);
        float* orow = out + (long)b * (CC + 1);
        float vmax = NEG_INF; int imax = 0;
        for (int i = lane; i < CC / 4; i += 32) {
            const float4 v = __ldg(&yr[i]);
            const int c = i * 4;
            orow[c] = v.x; orow[c + 1] = v.y; orow[c + 2] = v.z; orow[c + 3] = v.w;
            if (v.x > vmax) { vmax = v.x; imax = c; }
            if (v.y > vmax) { vmax = v.y; imax = c + 1; }
            if (v.z > vmax) { vmax = v.z; imax = c + 2; }
            if (v.w > vmax) { vmax = v.w; imax = c + 3; }
        }
        #pragma unroll
        for (int o = 16; o > 0; o >>= 1) {
            const float v2 = __shfl_xor_sync(0xffffffffu, vmax, o);
            const int   i2 = __shfl_xor_sync(0xffffffffu, imax, o);
            if (v2 > vmax || (v2 == vmax && i2 < imax)) { vmax = v2; imax = i2; }
        }
        if (lane == 0) { g_ymax[b] = vmax; g_jmax[b] = imax; }
    } else if (warp < BB + CC) {
        const int c = warp - BB;
        const float4* wr = (const float4*)(w + (long)c * HH);
        float s = 0.f;
        #pragma unroll
        for (int i = lane; i < HH / 4; i += 32) {
            const float4 v = __ldg(&wr[i]);
            s = fmaf(v.x, v.x, fmaf(v.y, v.y, fmaf(v.z, v.z, fmaf(v.w, v.w, s))));
        }
        #pragma unroll
        for (int o = 16; o > 0; o >>= 1)
            s += __shfl_xor_sync(0xffffffffu, s, o);
        if (lane == 0) g_norm[c] = s;
    }
}

// ---------------------------------------------------------------------------
// k_gram: G = w @ w^T, upper-triangular 64x64 tiles (136 blocks), full K=512,
// BK=32, double-buffered LDG pipeline, FFMA2 packed along K, mirror epilogue.
// ---------------------------------------------------------------------------
#define NT 16
#define BK 32
#define NKS (HH / BK)   // 16
#define SROW 34         // smem row stride in words (even: LDS.64-aligned;
                        // 34 mod 32 = 2 -> B-column reads conflict-free)

__global__ void __launch_bounds__(128, 1)
k_gram(const float* __restrict__ w) {
    int p = blockIdx.x;
    int ti = 0;
    while (p >= NT - ti) { p -= NT - ti; ti++; }
    const int tj = ti + p;

    __shared__ float As[64 * SROW];
    __shared__ float Bs[64 * SROW];

    const int t = threadIdx.x;
    // loader mapping: 128B-coalesced LDG.128
    const int lrow = t >> 3;        // 0..15
    const int seg  = t & 7;         // 0..7 (16B chunk within 128B row-chunk)
    // compute mapping: micro-tile 8 rows x {tc, tc+16, tc+32, tc+48}
    const int tr8 = (t >> 4) * 8;   // 0..56
    const int tc  = t & 15;

    const float* pA[4];
    const float* pB[4];
    #pragma unroll
    for (int m = 0; m < 4; m++) {
        const int ra = min(ti * 64 + lrow + 16 * m, CC - 1);
        const int rb = min(tj * 64 + lrow + 16 * m, CC - 1);
        pA[m] = w + (long)ra * HH + seg * 4;
        pB[m] = w + (long)rb * HH + seg * 4;
    }

    ull acc[8][4];
    #pragma unroll
    for (int i = 0; i < 8; i++)
        #pragma unroll
        for (int g = 0; g < 4; g++) acc[i][g] = 0ull;

    float4 ra4[4], rb4[4];
    #pragma unroll
    for (int m = 0; m < 4; m++) {
        ra4[m] = *(const float4*)(pA[m]);
        rb4[m] = *(const float4*)(pB[m]);
    }

    #pragma unroll 1
    for (int ks = 0; ks < NKS; ks++) {
        __syncthreads();                       // previous tile fully consumed
        #pragma unroll
        for (int m = 0; m < 4; m++) {
            const int base = (lrow + 16 * m) * SROW + seg * 4;
            *(float2*)&As[base]     = make_float2(ra4[m].x, ra4[m].y);
            *(float2*)&As[base + 2] = make_float2(ra4[m].z, ra4[m].w);
            *(float2*)&Bs[base]     = make_float2(rb4[m].x, rb4[m].y);
            *(float2*)&Bs[base + 2] = make_float2(rb4[m].z, rb4[m].w);
        }
        __syncthreads();

        if (ks + 1 < NKS) {                    // prefetch next K-slab (overlaps compute)
            const int off = (ks + 1) * BK;
            #pragma unroll
            for (int m = 0; m < 4; m++) {
                ra4[m] = *(const float4*)(pA[m] + off);
                rb4[m] = *(const float4*)(pB[m] + off);
            }
        }

        #pragma unroll
        for (int kk = 0; kk < BK / 2; kk++) {  // K handled in packed pairs
            ull a[8], b[4];
            #pragma unroll
            for (int i = 0; i < 8; i++)
                a[i] = *(const ull*)&As[(tr8 + i) * SROW + 2 * kk];
            #pragma unroll
            for (int g = 0; g < 4; g++)
                b[g] = *(const ull*)&Bs[(tc + 16 * g) * SROW + 2 * kk];
            #pragma unroll
            for (int i = 0; i < 8; i++)
                #pragma unroll
                for (int g = 0; g < 4; g++)
                    fma2(acc[i][g], a[i], b[g]);
        }
    }

    float res[8][4];
    #pragma unroll
    for (int i = 0; i < 8; i++)
        #pragma unroll
        for (int g = 0; g < 4; g++)
            res[i][g] = lo32(acc[i][g]) + hi32(acc[i][g]);

    const int gr = ti * 64 + tr8;
    const int gc = tj * 64 + tc;
    // direct store (upper tile): per instr = 2 rows x 16 consecutive floats
    #pragma unroll
    for (int i = 0; i < 8; i++)
        #pragma unroll
        for (int g = 0; g < 4; g++)
            g_G[(long)(gr + i) * 1024 + gc + 16 * g] = res[i][g];
    // mirror store (lower tile): float4 down the row dimension.
    // Diagonal tiles double-write bitwise-identical values (benign).
    #pragma unroll
    for (int g = 0; g < 4; g++) {
        const long mrow = (long)(gc + 16 * g) * 1024;
        float4 v0, v1;
        v0.x = res[0][g]; v0.y = res[1][g]; v0.z = res[2][g]; v0.w = res[3][g];
        v1.x = res[4][g]; v1.y = res[5][g]; v1.z = res[6][g]; v1.w = res[7][g];
        *(float4*)&g_G[mrow + gr]     = v0;
        *(float4*)&g_G[mrow + gr + 4] = v1;
    }
}

// ---------------------------------------------------------------------------
// k_bot: warp-per-row, coalesced float4 reads of G row j, pruned sqrt.
// ---------------------------------------------------------------------------
__global__ void k_bot(const float* __restrict__ y,
                      const float* __restrict__ eps_p,
                      const float* __restrict__ lip_p,
                      float* __restrict__ out) {
    const int b    = (blockIdx.x * blockDim.x + threadIdx.x) >> 5;
    const int lane = threadIdx.x & 31;
    if (b >= BB) return;

    const float s  = (*eps_p) * fabsf(*lip_p);
    const float s2 = s * s;

    const int   j    = g_jmax[b];
    const float ymax = g_ymax[b];
    const float nj   = g_norm[j];
    const float4* yr = (const float4*)(y + (long)b * CC);
    const float4* gr = (const float4*)(g_G + (long)j * 1024);
    const float4* nr = (const float4*)g_norm;

    float best = NEG_INF;
    for (int i = lane; i < CC / 4; i += 32) {
        const float4 yv = __ldg(&yr[i]);
        const float4 gv = gr[i];
        const float4 nv = nr[i];
        #pragma unroll
        for (int e = 0; e < 4; e++) {
            const float yve = (e == 0) ? yv.x : (e == 1) ? yv.y : (e == 2) ? yv.z : yv.w;
            const float gve = (e == 0) ? gv.x : (e == 1) ? gv.y : (e == 2) ? gv.z : gv.w;
            const float nve = (e == 0) ? nv.x : (e == 1) ? nv.y : (e == 2) ? nv.z : nv.w;
            if (yve == ymax) continue;           // ref masks y==ymax to -inf
            float sq = fmaf(-2.f, gve, nj + nve);
            if (sq < 0.f) sq = 0.f;
            const float d = best - yve;
            // safe skip: val <= yve + |s|*sqrt(sq) <= best when d>0 and sq*s2<=d^2
            if (d <= 0.f || sq * s2 > d * d) {
                best = fmaxf(best, fmaf(s, sqrtf(sq), yve));
            }
        }
    }
    #pragma unroll
    for (int o = 16; o > 0; o >>= 1)
        best = fmaxf(best, __shfl_xor_sync(0xffffffffu, best, o));
    if (lane == 0) out[(long)b * (CC + 1) + CC] = best;
}

// ---------------------------------------------------------------------------
extern "C" void kernel_launch(void* const* d_in, const int* in_sizes, int n_in,
                              void* d_out, int out_size) {
    const float* y   = (const float*)d_in[0];
    const float* w   = (const float*)d_in[1];
    const float* eps = (const float*)d_in[2];
    const float* lip = (const float*)d_in[3];
    float* out = (float*)d_out;

    k_prep<<<(32 * (BB + CC) + 255) / 256, 256>>>(y, w, out);
    k_gram<<<NT * (NT + 1) / 2, 128>>>(w);
    k_bot<<<(32 * BB + 255) / 256, 256>>>(y, eps, lip, out);
}